// round 2
// baseline (speedup 1.0000x reference)
#include <cuda_runtime.h>
#include <cuda_bf16.h>
#include <cstdint>

#define N_NODES 100000
#define N_EDGES 3200000
#define BATCH   16
#define HIDDEN  64

// Scratch (device globals: no allocation allowed in kernel_launch)
// 16B alignment is required for float4 loads and red.global.add.v4.f32.
__device__ __align__(16) float g_muT[(size_t)N_NODES * BATCH];   // mu transposed: [N][B]
__device__ __align__(16) float g_agg[(size_t)N_NODES * BATCH];   // scatter accumulator: [N][B]
__device__ float g_deg[N_NODES];                                 // degree counts

// ---------------------------------------------------------------------------
// Kernel 1: transpose mu [B][N] -> muT [N][B] (so each edge gather is one
// contiguous 64B row), and zero agg/deg. One block = 64 nodes, 256 threads.
// ---------------------------------------------------------------------------
__global__ void prep_kernel(const float* __restrict__ mu) {
    __shared__ float tile[BATCH][64 + 1];
    const int n0 = blockIdx.x * 64;
    const int t  = threadIdx.x;  // 256 threads

    #pragma unroll
    for (int i = t; i < BATCH * 64; i += 256) {
        const int b = i >> 6;       // i / 64
        const int j = i & 63;       // i % 64
        const int n = n0 + j;
        tile[b][j] = (n < N_NODES) ? mu[(size_t)b * N_NODES + n] : 0.0f;
    }
    __syncthreads();

    // each thread writes one float4 of muT (4 batches of one node)
    const int node = t >> 2;        // 0..63
    const int q    = t & 3;         // which float4 within the 16-wide row
    const int n    = n0 + node;
    if (n < N_NODES) {
        float4 v = make_float4(tile[q * 4 + 0][node],
                               tile[q * 4 + 1][node],
                               tile[q * 4 + 2][node],
                               tile[q * 4 + 3][node]);
        reinterpret_cast<float4*>(g_muT)[(size_t)n * 4 + q] = v;
        reinterpret_cast<float4*>(g_agg)[(size_t)n * 4 + q] = make_float4(0.f, 0.f, 0.f, 0.f);
        if (q == 0) g_deg[n] = 0.0f;
    }
}

// ---------------------------------------------------------------------------
// Kernel 2: per-edge scatter. Gather muT[col] (64B contiguous), reduce into
// agg[row] with 4x red.global.add.v4.f32 (no return value -> no scoreboard
// stall), count degree with a scalar red.
// edge_index is int32 in storage (JAX default x64-disabled downcasts int64).
// ---------------------------------------------------------------------------
__device__ __forceinline__ void red_add_v4(float* gptr, float4 v) {
    asm volatile("red.global.add.v4.f32 [%0], {%1, %2, %3, %4};"
                 :: "l"(__cvta_generic_to_global(gptr)),
                    "f"(v.x), "f"(v.y), "f"(v.z), "f"(v.w)
                 : "memory");
}

__global__ void __launch_bounds__(256) edge_kernel(const int* __restrict__ ei) {
    const int e = blockIdx.x * blockDim.x + threadIdx.x;
    if (e >= N_EDGES) return;

    const int r = ei[e];             // destination (row)
    const int c = ei[N_EDGES + e];   // source (col)
    if ((unsigned)r >= N_NODES || (unsigned)c >= N_NODES) return;  // safety guard

    const float4* src = reinterpret_cast<const float4*>(g_muT) + (size_t)c * 4;
    float4 v0 = src[0];
    float4 v1 = src[1];
    float4 v2 = src[2];
    float4 v3 = src[3];

    float* dst = g_agg + (size_t)r * BATCH;
    red_add_v4(dst + 0,  v0);
    red_add_v4(dst + 4,  v1);
    red_add_v4(dst + 8,  v2);
    red_add_v4(dst + 12, v3);

    asm volatile("red.global.add.f32 [%0], %1;"
                 :: "l"(__cvta_generic_to_global(g_deg + r)), "f"(1.0f)
                 : "memory");
}

// ---------------------------------------------------------------------------
// Kernel 3: mean + MLP (1 -> 64 GELU(erf) -> 1), per scalar.
// One block = 64 nodes x 16 batches = 1024 threads. agg read is fully
// coalesced; output write staged through shared for coalescing.
// ---------------------------------------------------------------------------
__global__ void __launch_bounds__(1024) mlp_kernel(const float* __restrict__ W1,
                                                   const float* __restrict__ b1,
                                                   const float* __restrict__ W2,
                                                   const float* __restrict__ b2,
                                                   float* __restrict__ out) {
    __shared__ float sW1[HIDDEN], sB1[HIDDEN], sW2[HIDDEN];
    __shared__ float tileY[BATCH][64 + 1];

    const int t = threadIdx.x;
    if (t < HIDDEN) {
        sW1[t] = W1[t];
        sB1[t] = b1[t];
        sW2[t] = W2[t];
    }
    __syncthreads();

    const int n0   = blockIdx.x * 64;
    const int node = t >> 4;   // t / 16
    const int b    = t & 15;   // t % 16
    const int n    = n0 + node;

    float y = 0.0f;
    if (n < N_NODES) {
        const float invd = 1.0f / fmaxf(g_deg[n], 1.0f);
        const float x = g_agg[(size_t)n * BATCH + b] * invd;
        float acc = b2[0];
        #pragma unroll
        for (int h = 0; h < HIDDEN; h++) {
            const float z = fmaf(x, sW1[h], sB1[h]);
            // exact (erf) GELU
            const float g = 0.5f * z * (1.0f + erff(z * 0.70710678118654752440f));
            acc = fmaf(g, sW2[h], acc);
        }
        y = acc;
    }
    tileY[b][node] = y;
    __syncthreads();

    // coalesced write-out: out[b][n] with n contiguous per warp
    const int bb = t >> 6;   // t / 64
    const int j  = t & 63;   // t % 64
    const int nn = n0 + j;
    if (nn < N_NODES) out[(size_t)bb * N_NODES + nn] = tileY[bb][j];
}

// ---------------------------------------------------------------------------
extern "C" void kernel_launch(void* const* d_in, const int* in_sizes, int n_in,
                              void* d_out, int out_size) {
    const float* mu = (const float*)d_in[0];
    const int*   ei = (const int*)d_in[1];     // edge_index stored as int32
    const float* W1 = (const float*)d_in[2];
    const float* b1 = (const float*)d_in[3];
    const float* W2 = (const float*)d_in[4];
    const float* b2 = (const float*)d_in[5];
    float*      out = (float*)d_out;

    const int nodeBlocks = (N_NODES + 63) / 64;            // 1563
    prep_kernel<<<nodeBlocks, 256>>>(mu);

    const int edgeBlocks = (N_EDGES + 255) / 256;          // 12500
    edge_kernel<<<edgeBlocks, 256>>>(ei);

    mlp_kernel<<<nodeBlocks, 1024>>>(W1, b1, W2, b2, out);
}

// round 3
// speedup vs baseline: 1.7324x; 1.7324x over previous
#include <cuda_runtime.h>
#include <cuda_bf16.h>
#include <cstdint>

#define N_NODES 100000
#define N_EDGES 3200000
#define BATCH   16
#define HIDDEN  64

// Lookup table for the scalar MLP f(x): 1 -> 64 GELU(erf) -> 1
#define TBL_N     16384
#define TBL_RANGE 10.0f
#define TBL_SCALE ((float)TBL_N / (2.0f * TBL_RANGE))   // 819.2
#define TBL_OFF   ((float)TBL_N * 0.5f)                 // 8192

// Scratch (device globals: no allocation allowed in kernel_launch)
__device__ __align__(16) float g_muT[(size_t)N_NODES * BATCH];   // mu transposed: [N][B]
__device__ __align__(16) float g_agg[(size_t)N_NODES * BATCH];   // scatter accumulator: [N][B]
__device__ float g_deg[N_NODES];                                 // degree counts
__device__ float g_tbl[TBL_N + 2];                               // f(x) samples

// ---------------------------------------------------------------------------
// Exact scalar MLP (erf GELU) — used for table build + rare out-of-range path.
// ---------------------------------------------------------------------------
__device__ __forceinline__ float mlp_exact(float x,
                                           const float* __restrict__ W1,
                                           const float* __restrict__ b1,
                                           const float* __restrict__ W2,
                                           const float* __restrict__ b2) {
    float acc = b2[0];
    #pragma unroll 8
    for (int h = 0; h < HIDDEN; h++) {
        const float z = fmaf(x, __ldg(W1 + h), __ldg(b1 + h));
        const float g = 0.5f * z * (1.0f + erff(z * 0.70710678118654752440f));
        acc = fmaf(g, __ldg(W2 + h), acc);
    }
    return acc;
}

// ---------------------------------------------------------------------------
// Kernel 0: tabulate f(x) over [-TBL_RANGE, TBL_RANGE].
// ---------------------------------------------------------------------------
__global__ void table_kernel(const float* __restrict__ W1,
                             const float* __restrict__ b1,
                             const float* __restrict__ W2,
                             const float* __restrict__ b2) {
    const int i = blockIdx.x * blockDim.x + threadIdx.x;
    if (i > TBL_N) return;
    const float x = -TBL_RANGE + (2.0f * TBL_RANGE / (float)TBL_N) * (float)i;
    g_tbl[i] = mlp_exact(x, W1, b1, W2, b2);
}

// ---------------------------------------------------------------------------
// Kernel 1: transpose mu [B][N] -> muT [N][B] (each edge gather becomes one
// contiguous 64B row) and zero agg/deg. One block = 64 nodes, 256 threads.
// ---------------------------------------------------------------------------
__global__ void prep_kernel(const float* __restrict__ mu) {
    __shared__ float tile[BATCH][64 + 1];
    const int n0 = blockIdx.x * 64;
    const int t  = threadIdx.x;

    #pragma unroll
    for (int i = t; i < BATCH * 64; i += 256) {
        const int b = i >> 6;
        const int j = i & 63;
        const int n = n0 + j;
        tile[b][j] = (n < N_NODES) ? mu[(size_t)b * N_NODES + n] : 0.0f;
    }
    __syncthreads();

    const int node = t >> 2;
    const int q    = t & 3;
    const int n    = n0 + node;
    if (n < N_NODES) {
        float4 v = make_float4(tile[q * 4 + 0][node],
                               tile[q * 4 + 1][node],
                               tile[q * 4 + 2][node],
                               tile[q * 4 + 3][node]);
        reinterpret_cast<float4*>(g_muT)[(size_t)n * 4 + q] = v;
        reinterpret_cast<float4*>(g_agg)[(size_t)n * 4 + q] = make_float4(0.f, 0.f, 0.f, 0.f);
        if (q == 0) g_deg[n] = 0.0f;
    }
}

// ---------------------------------------------------------------------------
// Kernel 2: per-edge scatter. Gather muT[col] (64B contiguous), reduce into
// agg[row] with 4x red.global.add.v4.f32, count degree with a scalar red.
// ---------------------------------------------------------------------------
__device__ __forceinline__ void red_add_v4(float* gptr, float4 v) {
    asm volatile("red.global.add.v4.f32 [%0], {%1, %2, %3, %4};"
                 :: "l"(__cvta_generic_to_global(gptr)),
                    "f"(v.x), "f"(v.y), "f"(v.z), "f"(v.w)
                 : "memory");
}

__global__ void __launch_bounds__(256) edge_kernel(const int* __restrict__ ei) {
    const int e = blockIdx.x * blockDim.x + threadIdx.x;
    if (e >= N_EDGES) return;

    const int r = ei[e];             // destination (row)
    const int c = ei[N_EDGES + e];   // source (col)
    if ((unsigned)r >= N_NODES || (unsigned)c >= N_NODES) return;

    const float4* src = reinterpret_cast<const float4*>(g_muT) + (size_t)c * 4;
    float4 v0 = src[0];
    float4 v1 = src[1];
    float4 v2 = src[2];
    float4 v3 = src[3];

    float* dst = g_agg + (size_t)r * BATCH;
    red_add_v4(dst + 0,  v0);
    red_add_v4(dst + 4,  v1);
    red_add_v4(dst + 8,  v2);
    red_add_v4(dst + 12, v3);

    asm volatile("red.global.add.f32 [%0], %1;"
                 :: "l"(__cvta_generic_to_global(g_deg + r)), "f"(1.0f)
                 : "memory");
}

// ---------------------------------------------------------------------------
// Kernel 3: mean + table-interp MLP. One block = 64 nodes x 16 batches.
// agg read coalesced; table lookups hit L1 (64KB table fits in 228KB L1).
// ---------------------------------------------------------------------------
__global__ void __launch_bounds__(1024) mlp_kernel(const float* __restrict__ W1,
                                                   const float* __restrict__ b1,
                                                   const float* __restrict__ W2,
                                                   const float* __restrict__ b2,
                                                   float* __restrict__ out) {
    __shared__ float tileY[BATCH][64 + 1];

    const int t    = threadIdx.x;
    const int n0   = blockIdx.x * 64;
    const int node = t >> 4;
    const int b    = t & 15;
    const int n    = n0 + node;

    float y = 0.0f;
    if (n < N_NODES) {
        const float invd = 1.0f / fmaxf(g_deg[n], 1.0f);
        const float x = g_agg[(size_t)n * BATCH + b] * invd;
        const float u = fmaf(x, TBL_SCALE, TBL_OFF);
        if (u >= 0.0f && u < (float)TBL_N) {
            const int   i    = (int)u;
            const float frac = u - (float)i;
            const float t0 = __ldg(g_tbl + i);
            const float t1 = __ldg(g_tbl + i + 1);
            y = fmaf(t1 - t0, frac, t0);
        } else {
            y = mlp_exact(x, W1, b1, W2, b2);   // |x| > 10: essentially never
        }
    }
    tileY[b][node] = y;
    __syncthreads();

    const int bb = t >> 6;
    const int j  = t & 63;
    const int nn = n0 + j;
    if (nn < N_NODES) out[(size_t)bb * N_NODES + nn] = tileY[bb][j];
}

// ---------------------------------------------------------------------------
extern "C" void kernel_launch(void* const* d_in, const int* in_sizes, int n_in,
                              void* d_out, int out_size) {
    const float* mu = (const float*)d_in[0];
    const int*   ei = (const int*)d_in[1];     // edge_index stored as int32
    const float* W1 = (const float*)d_in[2];
    const float* b1 = (const float*)d_in[3];
    const float* W2 = (const float*)d_in[4];
    const float* b2 = (const float*)d_in[5];
    float*      out = (float*)d_out;

    table_kernel<<<(TBL_N + 256) / 256, 256>>>(W1, b1, W2, b2);

    const int nodeBlocks = (N_NODES + 63) / 64;            // 1563
    prep_kernel<<<nodeBlocks, 256>>>(mu);

    const int edgeBlocks = (N_EDGES + 255) / 256;          // 12500
    edge_kernel<<<edgeBlocks, 256>>>(ei);

    mlp_kernel<<<nodeBlocks, 1024>>>(W1, b1, W2, b2, out);
}

// round 4
// speedup vs baseline: 1.7580x; 1.0148x over previous
#include <cuda_runtime.h>
#include <cuda_bf16.h>
#include <cstdint>

#define N_NODES 100000
#define N_EDGES 3200000
#define BATCH   16
#define HIDDEN  64

#define SCAN_BLK   1024
#define SCAN_NBLK  ((N_NODES + SCAN_BLK - 1) / SCAN_BLK)   // 98

// Lookup table for the scalar MLP f(x): 1 -> 64 GELU(erf) -> 1
#define TBL_N     16384
#define TBL_RANGE 10.0f
#define TBL_SCALE ((float)TBL_N / (2.0f * TBL_RANGE))
#define TBL_OFF   ((float)TBL_N * 0.5f)

// Scratch (device globals)
__device__ __align__(16) float g_muT[(size_t)N_NODES * BATCH];  // mu transposed [N][B]
__device__ unsigned g_cnt[N_NODES];            // per-dest edge counts (histogram)
__device__ unsigned g_rowptr[N_NODES + 1];     // CSR row pointers
__device__ unsigned g_cursor[N_NODES];         // scatter cursors
__device__ unsigned g_bsum[SCAN_NBLK];         // block sums for scan
__device__ unsigned g_bsumx[SCAN_NBLK];        // exclusive-scanned block sums
__device__ int      g_scol[N_EDGES];           // CSR column (source) ids
__device__ float    g_tbl[TBL_N + 2];          // f(x) samples

// ---------------------------------------------------------------------------
// Exact scalar MLP (erf GELU) — table build + out-of-range fallback.
// ---------------------------------------------------------------------------
__device__ __forceinline__ float mlp_exact(float x,
                                           const float* __restrict__ W1,
                                           const float* __restrict__ b1,
                                           const float* __restrict__ W2,
                                           const float* __restrict__ b2) {
    float acc = b2[0];
    #pragma unroll 8
    for (int h = 0; h < HIDDEN; h++) {
        const float z = fmaf(x, __ldg(W1 + h), __ldg(b1 + h));
        const float g = 0.5f * z * (1.0f + erff(z * 0.70710678118654752440f));
        acc = fmaf(g, __ldg(W2 + h), acc);
    }
    return acc;
}

__global__ void table_kernel(const float* __restrict__ W1,
                             const float* __restrict__ b1,
                             const float* __restrict__ W2,
                             const float* __restrict__ b2) {
    const int i = blockIdx.x * blockDim.x + threadIdx.x;
    if (i > TBL_N) return;
    const float x = -TBL_RANGE + (2.0f * TBL_RANGE / (float)TBL_N) * (float)i;
    g_tbl[i] = mlp_exact(x, W1, b1, W2, b2);
}

// ---------------------------------------------------------------------------
// Kernel 1: transpose mu [B][N] -> muT [N][B]; zero histogram counters.
// ---------------------------------------------------------------------------
__global__ void prep_kernel(const float* __restrict__ mu) {
    __shared__ float tile[BATCH][64 + 1];
    const int n0 = blockIdx.x * 64;
    const int t  = threadIdx.x;   // 256

    #pragma unroll
    for (int i = t; i < BATCH * 64; i += 256) {
        const int b = i >> 6;
        const int j = i & 63;
        const int n = n0 + j;
        tile[b][j] = (n < N_NODES) ? mu[(size_t)b * N_NODES + n] : 0.0f;
    }
    __syncthreads();

    const int node = t >> 2;
    const int q    = t & 3;
    const int n    = n0 + node;
    if (n < N_NODES) {
        float4 v = make_float4(tile[q * 4 + 0][node],
                               tile[q * 4 + 1][node],
                               tile[q * 4 + 2][node],
                               tile[q * 4 + 3][node]);
        reinterpret_cast<float4*>(g_muT)[(size_t)n * 4 + q] = v;
        if (q == 0) g_cnt[n] = 0u;
    }
}

// ---------------------------------------------------------------------------
// Kernel 2: histogram of destination nodes (int REDs, spread addresses).
// ---------------------------------------------------------------------------
__global__ void __launch_bounds__(256) hist_kernel(const int* __restrict__ ei) {
    const int e = blockIdx.x * blockDim.x + threadIdx.x;
    if (e >= N_EDGES) return;
    const int r = ei[e];
    if ((unsigned)r < N_NODES) atomicAdd(&g_cnt[r], 1u);
}

// ---------------------------------------------------------------------------
// Exclusive prefix scan over g_cnt -> g_rowptr (3 small kernels).
// ---------------------------------------------------------------------------
__global__ void __launch_bounds__(SCAN_BLK) scan1_kernel() {
    __shared__ unsigned s[SCAN_BLK];
    const int t = threadIdx.x;
    const int i = blockIdx.x * SCAN_BLK + t;
    const unsigned v = (i < N_NODES) ? g_cnt[i] : 0u;
    s[t] = v;
    __syncthreads();
    #pragma unroll
    for (int off = 1; off < SCAN_BLK; off <<= 1) {
        const unsigned u = (t >= off) ? s[t - off] : 0u;
        __syncthreads();
        s[t] += u;
        __syncthreads();
    }
    if (i < N_NODES) g_rowptr[i] = s[t] - v;   // exclusive
    if (t == SCAN_BLK - 1) g_bsum[blockIdx.x] = s[t];
}

__global__ void scan2_kernel() {
    __shared__ unsigned s[128];
    const int t = threadIdx.x;   // 128 >= SCAN_NBLK
    const unsigned v = (t < SCAN_NBLK) ? g_bsum[t] : 0u;
    s[t] = v;
    __syncthreads();
    #pragma unroll
    for (int off = 1; off < 128; off <<= 1) {
        const unsigned u = (t >= off) ? s[t - off] : 0u;
        __syncthreads();
        s[t] += u;
        __syncthreads();
    }
    if (t < SCAN_NBLK) g_bsumx[t] = s[t] - v;  // exclusive
}

__global__ void __launch_bounds__(SCAN_BLK) scan3_kernel() {
    const int i = blockIdx.x * SCAN_BLK + threadIdx.x;
    if (i < N_NODES) {
        const unsigned p = g_rowptr[i] + g_bsumx[blockIdx.x];
        g_rowptr[i] = p;
        g_cursor[i] = p;
    }
    if (i == 0) g_rowptr[N_NODES] = (unsigned)N_EDGES;
}

// ---------------------------------------------------------------------------
// Kernel 3: scatter source ids into CSR order.
// ---------------------------------------------------------------------------
__global__ void __launch_bounds__(256) scatter_kernel(const int* __restrict__ ei) {
    const int e = blockIdx.x * blockDim.x + threadIdx.x;
    if (e >= N_EDGES) return;
    const int r = ei[e];
    const int c = ei[N_EDGES + e];
    if ((unsigned)r >= N_NODES || (unsigned)c >= N_NODES) return;
    const unsigned pos = atomicAdd(&g_cursor[r], 1u);
    g_scol[pos] = c;
}

// ---------------------------------------------------------------------------
// Kernel 4: fused gather-reduce + mean + LUT MLP + coalesced write.
// One half-warp (16 lanes = 16 batches) per node; 64 nodes per 1024-thr block.
// Each loop iteration: 1 broadcast scol load + one coalesced 64B muT row.
// ---------------------------------------------------------------------------
__global__ void __launch_bounds__(1024) reduce_mlp_kernel(const float* __restrict__ W1,
                                                          const float* __restrict__ b1,
                                                          const float* __restrict__ W2,
                                                          const float* __restrict__ b2,
                                                          float* __restrict__ out) {
    __shared__ float tileY[BATCH][64 + 1];

    const int t    = threadIdx.x;
    const int n0   = blockIdx.x * 64;
    const int node = t >> 4;
    const int b    = t & 15;
    const int n    = n0 + node;

    float y = 0.0f;
    if (n < N_NODES) {
        const unsigned start = g_rowptr[n];
        const unsigned end   = g_rowptr[n + 1];

        float acc = 0.0f;
        unsigned i = start;
        // unroll-by-4: four independent gathers in flight per iteration
        for (; i + 4 <= end; i += 4) {
            const int c0 = g_scol[i + 0];
            const int c1 = g_scol[i + 1];
            const int c2 = g_scol[i + 2];
            const int c3 = g_scol[i + 3];
            const float v0 = g_muT[(size_t)c0 * BATCH + b];
            const float v1 = g_muT[(size_t)c1 * BATCH + b];
            const float v2 = g_muT[(size_t)c2 * BATCH + b];
            const float v3 = g_muT[(size_t)c3 * BATCH + b];
            acc += (v0 + v1) + (v2 + v3);
        }
        for (; i < end; i++) {
            acc += g_muT[(size_t)g_scol[i] * BATCH + b];
        }

        const unsigned deg = end - start;
        const float invd = 1.0f / (float)(deg ? deg : 1u);
        const float x = acc * invd;

        const float u = fmaf(x, TBL_SCALE, TBL_OFF);
        if (u >= 0.0f && u < (float)TBL_N) {
            const int   idx  = (int)u;
            const float frac = u - (float)idx;
            const float t0 = __ldg(g_tbl + idx);
            const float t1 = __ldg(g_tbl + idx + 1);
            y = fmaf(t1 - t0, frac, t0);
        } else {
            y = mlp_exact(x, W1, b1, W2, b2);
        }
    }
    tileY[b][node] = y;
    __syncthreads();

    const int bb = t >> 6;
    const int j  = t & 63;
    const int nn = n0 + j;
    if (nn < N_NODES) out[(size_t)bb * N_NODES + nn] = tileY[bb][j];
}

// ---------------------------------------------------------------------------
extern "C" void kernel_launch(void* const* d_in, const int* in_sizes, int n_in,
                              void* d_out, int out_size) {
    const float* mu = (const float*)d_in[0];
    const int*   ei = (const int*)d_in[1];     // edge_index stored as int32
    const float* W1 = (const float*)d_in[2];
    const float* b1 = (const float*)d_in[3];
    const float* W2 = (const float*)d_in[4];
    const float* b2 = (const float*)d_in[5];
    float*      out = (float*)d_out;

    const int nodeBlocks = (N_NODES + 63) / 64;      // 1563
    const int edgeBlocks = (N_EDGES + 255) / 256;    // 12500

    table_kernel<<<(TBL_N + 256) / 256, 256>>>(W1, b1, W2, b2);
    prep_kernel<<<nodeBlocks, 256>>>(mu);
    hist_kernel<<<edgeBlocks, 256>>>(ei);
    scan1_kernel<<<SCAN_NBLK, SCAN_BLK>>>();
    scan2_kernel<<<1, 128>>>();
    scan3_kernel<<<SCAN_NBLK, SCAN_BLK>>>();
    scatter_kernel<<<edgeBlocks, 256>>>(ei);
    reduce_mlp_kernel<<<nodeBlocks, 1024>>>(W1, b1, W2, b2, out);
}

// round 5
// speedup vs baseline: 2.3671x; 1.3465x over previous
#include <cuda_runtime.h>
#include <cuda_bf16.h>
#include <cstdint>

#define N_NODES 100000
#define N_EDGES 3200000
#define BATCH   16
#define HIDDEN  64

// Lookup table for the scalar MLP f(x): 1 -> 64 GELU(erf) -> 1
#define TBL_N     16384
#define TBL_RANGE 10.0f
#define TBL_SCALE ((float)TBL_N / (2.0f * TBL_RANGE))
#define TBL_OFF   ((float)TBL_N * 0.5f)

// Scratch (device globals; no allocation allowed in kernel_launch)
__device__ __align__(16) float g_muT[(size_t)N_NODES * BATCH];  // mu transposed [N][B]
__device__ __align__(16) float g_agg[(size_t)N_NODES * BATCH];  // accumulators  [N][B]
__device__ float g_deg[N_NODES];                                // degree counts
__device__ float g_tbl[TBL_N + 2];                              // f(x) samples

// ---------------------------------------------------------------------------
// Exact scalar MLP (erf GELU) — table build + rare out-of-range fallback.
// ---------------------------------------------------------------------------
__device__ __forceinline__ float mlp_exact(float x,
                                           const float* __restrict__ W1,
                                           const float* __restrict__ b1,
                                           const float* __restrict__ W2,
                                           const float* __restrict__ b2) {
    float acc = b2[0];
    #pragma unroll 8
    for (int h = 0; h < HIDDEN; h++) {
        const float z = fmaf(x, __ldg(W1 + h), __ldg(b1 + h));
        const float g = 0.5f * z * (1.0f + erff(z * 0.70710678118654752440f));
        acc = fmaf(g, __ldg(W2 + h), acc);
    }
    return acc;
}

__global__ void table_kernel(const float* __restrict__ W1,
                             const float* __restrict__ b1,
                             const float* __restrict__ W2,
                             const float* __restrict__ b2) {
    const int i = blockIdx.x * blockDim.x + threadIdx.x;
    if (i > TBL_N) return;
    const float x = -TBL_RANGE + (2.0f * TBL_RANGE / (float)TBL_N) * (float)i;
    g_tbl[i] = mlp_exact(x, W1, b1, W2, b2);
}

// ---------------------------------------------------------------------------
// Kernel 1: transpose mu [B][N] -> muT [N][B]; zero agg and deg.
// One thread per node; 16 fully-coalesced strided reads (MLP=16, no barriers).
// ---------------------------------------------------------------------------
__global__ void __launch_bounds__(256) prep_kernel(const float* __restrict__ mu) {
    const int n = blockIdx.x * blockDim.x + threadIdx.x;
    if (n >= N_NODES) return;

    float v[BATCH];
    #pragma unroll
    for (int b = 0; b < BATCH; b++)
        v[b] = __ldg(mu + (size_t)b * N_NODES + n);

    float4* dst = reinterpret_cast<float4*>(g_muT) + (size_t)n * 4;
    dst[0] = make_float4(v[0],  v[1],  v[2],  v[3]);
    dst[1] = make_float4(v[4],  v[5],  v[6],  v[7]);
    dst[2] = make_float4(v[8],  v[9],  v[10], v[11]);
    dst[3] = make_float4(v[12], v[13], v[14], v[15]);

    const float4 z = make_float4(0.f, 0.f, 0.f, 0.f);
    float4* az = reinterpret_cast<float4*>(g_agg) + (size_t)n * 4;
    az[0] = z; az[1] = z; az[2] = z; az[3] = z;
    g_deg[n] = 0.0f;
}

// ---------------------------------------------------------------------------
// Kernel 2: per-edge scatter, 4 lanes per edge (8 edges per warp).
// Lane q of an edge moves float4 #q of the 64B row: the warp's LDG.128
// touches only 8 lines (vs 32) and the warp's RED touches only 8 lines,
// cutting L1tex wavefronts ~4x vs one-thread-per-edge.
// ---------------------------------------------------------------------------
__device__ __forceinline__ void red_add_v4(float* gptr, float4 v) {
    asm volatile("red.global.add.v4.f32 [%0], {%1, %2, %3, %4};"
                 :: "l"(__cvta_generic_to_global(gptr)),
                    "f"(v.x), "f"(v.y), "f"(v.z), "f"(v.w)
                 : "memory");
}

__global__ void __launch_bounds__(256) edge_kernel(const int* __restrict__ ei) {
    const int T = blockIdx.x * blockDim.x + threadIdx.x;
    const int e = T >> 2;        // edge id
    const int q = T & 3;         // float4 slot within the 64B row
    if (e >= N_EDGES) return;

    const int r = __ldg(ei + e);             // destination (row)
    const int c = __ldg(ei + N_EDGES + e);   // source (col)
    if ((unsigned)r >= N_NODES || (unsigned)c >= N_NODES) return;

    const float4 v = reinterpret_cast<const float4*>(g_muT)[(size_t)c * 4 + q];
    red_add_v4(g_agg + (size_t)r * BATCH + q * 4, v);

    if (q == 0) {
        asm volatile("red.global.add.f32 [%0], %1;"
                     :: "l"(__cvta_generic_to_global(g_deg + r)), "f"(1.0f)
                     : "memory");
    }
}

// ---------------------------------------------------------------------------
// Kernel 3: mean + table-interp MLP. One block = 64 nodes x 16 batches.
// agg read coalesced; table lookups hit L1; coalesced staged write-out.
// ---------------------------------------------------------------------------
__global__ void __launch_bounds__(1024) mlp_kernel(const float* __restrict__ W1,
                                                   const float* __restrict__ b1,
                                                   const float* __restrict__ W2,
                                                   const float* __restrict__ b2,
                                                   float* __restrict__ out) {
    __shared__ float tileY[BATCH][64 + 1];

    const int t    = threadIdx.x;
    const int n0   = blockIdx.x * 64;
    const int node = t >> 4;
    const int b    = t & 15;
    const int n    = n0 + node;

    float y = 0.0f;
    if (n < N_NODES) {
        const float invd = 1.0f / fmaxf(g_deg[n], 1.0f);
        const float x = g_agg[(size_t)n * BATCH + b] * invd;
        const float u = fmaf(x, TBL_SCALE, TBL_OFF);
        if (u >= 0.0f && u < (float)TBL_N) {
            const int   i    = (int)u;
            const float frac = u - (float)i;
            const float t0 = __ldg(g_tbl + i);
            const float t1 = __ldg(g_tbl + i + 1);
            y = fmaf(t1 - t0, frac, t0);
        } else {
            y = mlp_exact(x, W1, b1, W2, b2);
        }
    }
    tileY[b][node] = y;
    __syncthreads();

    const int bb = t >> 6;
    const int j  = t & 63;
    const int nn = n0 + j;
    if (nn < N_NODES) out[(size_t)bb * N_NODES + nn] = tileY[bb][j];
}

// ---------------------------------------------------------------------------
extern "C" void kernel_launch(void* const* d_in, const int* in_sizes, int n_in,
                              void* d_out, int out_size) {
    const float* mu = (const float*)d_in[0];
    const int*   ei = (const int*)d_in[1];     // edge_index stored as int32
    const float* W1 = (const float*)d_in[2];
    const float* b1 = (const float*)d_in[3];
    const float* W2 = (const float*)d_in[4];
    const float* b2 = (const float*)d_in[5];
    float*      out = (float*)d_out;

    table_kernel<<<(TBL_N + 256) / 256, 256>>>(W1, b1, W2, b2);
    prep_kernel<<<(N_NODES + 255) / 256, 256>>>(mu);

    const long long lanes = (long long)N_EDGES * 4;
    edge_kernel<<<(int)((lanes + 255) / 256), 256>>>(ei);

    mlp_kernel<<<(N_NODES + 63) / 64, 1024>>>(W1, b1, W2, b2, out);
}

// round 6
// speedup vs baseline: 2.5770x; 1.0887x over previous
#include <cuda_runtime.h>
#include <cuda_bf16.h>
#include <cstdint>

#define N_NODES 100000
#define N_EDGES 3200000
#define BATCH   16
#define HIDDEN  64

// Lookup table for the scalar MLP f(x): 1 -> 64 GELU(erf) -> 1
#define TBL_N     16384
#define TBL_RANGE 10.0f
#define TBL_SCALE ((float)TBL_N / (2.0f * TBL_RANGE))
#define TBL_OFF   ((float)TBL_N * 0.5f)

#define TBL_BLOCKS  ((TBL_N + 1 + 255) / 256)       // 65
#define PREP_BLOCKS ((N_NODES + 255) / 256)         // 391

// Scratch (device globals; no allocation allowed in kernel_launch)
__device__ __align__(16) float g_muT[(size_t)N_NODES * BATCH];  // mu transposed [N][B]
__device__ __align__(16) float g_agg[(size_t)N_NODES * BATCH];  // accumulators  [N][B]
__device__ float g_deg[N_NODES];                                // degree counts
__device__ float g_tbl[TBL_N + 2];                              // f(x) samples

// ---------------------------------------------------------------------------
// Exact scalar MLP (erf GELU) — table build + rare out-of-range fallback.
// ---------------------------------------------------------------------------
__device__ __forceinline__ float mlp_exact(float x,
                                           const float* __restrict__ W1,
                                           const float* __restrict__ b1,
                                           const float* __restrict__ W2,
                                           const float* __restrict__ b2) {
    float acc = b2[0];
    #pragma unroll 8
    for (int h = 0; h < HIDDEN; h++) {
        const float z = fmaf(x, __ldg(W1 + h), __ldg(b1 + h));
        const float g = 0.5f * z * (1.0f + erff(z * 0.70710678118654752440f));
        acc = fmaf(g, __ldg(W2 + h), acc);
    }
    return acc;
}

__device__ __forceinline__ float lut_eval(float x,
                                          const float* __restrict__ W1,
                                          const float* __restrict__ b1,
                                          const float* __restrict__ W2,
                                          const float* __restrict__ b2) {
    const float u = fmaf(x, TBL_SCALE, TBL_OFF);
    if (u >= 0.0f && u < (float)TBL_N) {
        const int   i    = (int)u;
        const float frac = u - (float)i;
        const float t0 = __ldg(g_tbl + i);
        const float t1 = __ldg(g_tbl + i + 1);
        return fmaf(t1 - t0, frac, t0);
    }
    return mlp_exact(x, W1, b1, W2, b2);   // |x| > 10: essentially never
}

// ---------------------------------------------------------------------------
// Kernel 1 (merged): blocks [0, TBL_BLOCKS) build the LUT (pure MUFU/FMA);
// blocks [TBL_BLOCKS, ...) transpose mu [B][N] -> muT [N][B] and zero agg/deg
// (pure memory). The two halves overlap across SMs.
// ---------------------------------------------------------------------------
__global__ void __launch_bounds__(256) init_kernel(const float* __restrict__ mu,
                                                   const float* __restrict__ W1,
                                                   const float* __restrict__ b1,
                                                   const float* __restrict__ W2,
                                                   const float* __restrict__ b2) {
    if (blockIdx.x < TBL_BLOCKS) {
        const int i = blockIdx.x * 256 + threadIdx.x;
        if (i <= TBL_N) {
            const float x = -TBL_RANGE + (2.0f * TBL_RANGE / (float)TBL_N) * (float)i;
            g_tbl[i] = mlp_exact(x, W1, b1, W2, b2);
        }
        return;
    }

    const int n = (blockIdx.x - TBL_BLOCKS) * 256 + threadIdx.x;
    if (n >= N_NODES) return;

    float v[BATCH];
    #pragma unroll
    for (int b = 0; b < BATCH; b++)
        v[b] = __ldg(mu + (size_t)b * N_NODES + n);

    float4* dst = reinterpret_cast<float4*>(g_muT) + (size_t)n * 4;
    dst[0] = make_float4(v[0],  v[1],  v[2],  v[3]);
    dst[1] = make_float4(v[4],  v[5],  v[6],  v[7]);
    dst[2] = make_float4(v[8],  v[9],  v[10], v[11]);
    dst[3] = make_float4(v[12], v[13], v[14], v[15]);

    const float4 z = make_float4(0.f, 0.f, 0.f, 0.f);
    float4* az = reinterpret_cast<float4*>(g_agg) + (size_t)n * 4;
    az[0] = z; az[1] = z; az[2] = z; az[3] = z;
    g_deg[n] = 0.0f;
}

// ---------------------------------------------------------------------------
// Kernel 2: per-edge scatter, 4 lanes per edge (8 edges per warp).
// Warp's LDG.128 touches 8 lines and the warp's v4-RED touches 8 lines.
// ---------------------------------------------------------------------------
__device__ __forceinline__ void red_add_v4(float* gptr, float4 v) {
    asm volatile("red.global.add.v4.f32 [%0], {%1, %2, %3, %4};"
                 :: "l"(__cvta_generic_to_global(gptr)),
                    "f"(v.x), "f"(v.y), "f"(v.z), "f"(v.w)
                 : "memory");
}

__global__ void __launch_bounds__(256) edge_kernel(const int* __restrict__ ei) {
    const int T = blockIdx.x * blockDim.x + threadIdx.x;
    const int e = T >> 2;        // edge id
    const int q = T & 3;         // float4 slot within the 64B row
    if (e >= N_EDGES) return;

    const int r = __ldg(ei + e);             // destination (row)
    const int c = __ldg(ei + N_EDGES + e);   // source (col)
    if ((unsigned)r >= N_NODES || (unsigned)c >= N_NODES) return;

    const float4 v = reinterpret_cast<const float4*>(g_muT)[(size_t)c * 4 + q];
    red_add_v4(g_agg + (size_t)r * BATCH + q * 4, v);

    if (q == 0) {
        asm volatile("red.global.add.f32 [%0], %1;"
                     :: "l"(__cvta_generic_to_global(g_deg + r)), "f"(1.0f)
                     : "memory");
    }
}

// ---------------------------------------------------------------------------
// Kernel 3: mean + LUT MLP, vectorized: one thread = 4 batches of one node
// (float4 agg load). 512 threads = 128 nodes per block. Staged smem
// transpose for coalesced out[b][n] writes.
// ---------------------------------------------------------------------------
__global__ void __launch_bounds__(512) mlp_kernel(const float* __restrict__ W1,
                                                  const float* __restrict__ b1,
                                                  const float* __restrict__ W2,
                                                  const float* __restrict__ b2,
                                                  float* __restrict__ out) {
    __shared__ float tileY[BATCH][128 + 4];

    const int t    = threadIdx.x;
    const int n0   = blockIdx.x * 128;
    const int node = t >> 2;
    const int q    = t & 3;
    const int n    = n0 + node;

    float4 y = make_float4(0.f, 0.f, 0.f, 0.f);
    if (n < N_NODES) {
        const float invd = 1.0f / fmaxf(g_deg[n], 1.0f);
        const float4 a = reinterpret_cast<const float4*>(g_agg)[(size_t)n * 4 + q];
        y.x = lut_eval(a.x * invd, W1, b1, W2, b2);
        y.y = lut_eval(a.y * invd, W1, b1, W2, b2);
        y.z = lut_eval(a.z * invd, W1, b1, W2, b2);
        y.w = lut_eval(a.w * invd, W1, b1, W2, b2);
    }
    tileY[q * 4 + 0][node] = y.x;
    tileY[q * 4 + 1][node] = y.y;
    tileY[q * 4 + 2][node] = y.z;
    tileY[q * 4 + 3][node] = y.w;
    __syncthreads();

    const int j = t & 127;
    #pragma unroll
    for (int r = 0; r < 4; r++) {
        const int b  = (t >> 7) + r * 4;
        const int nn = n0 + j;
        if (nn < N_NODES) out[(size_t)b * N_NODES + nn] = tileY[b][j];
    }
}

// ---------------------------------------------------------------------------
extern "C" void kernel_launch(void* const* d_in, const int* in_sizes, int n_in,
                              void* d_out, int out_size) {
    const float* mu = (const float*)d_in[0];
    const int*   ei = (const int*)d_in[1];     // edge_index stored as int32
    const float* W1 = (const float*)d_in[2];
    const float* b1 = (const float*)d_in[3];
    const float* W2 = (const float*)d_in[4];
    const float* b2 = (const float*)d_in[5];
    float*      out = (float*)d_out;

    init_kernel<<<TBL_BLOCKS + PREP_BLOCKS, 256>>>(mu, W1, b1, W2, b2);

    const long long lanes = (long long)N_EDGES * 4;
    edge_kernel<<<(int)((lanes + 255) / 256), 256>>>(ei);

    mlp_kernel<<<(N_NODES + 127) / 128, 512>>>(W1, b1, W2, b2, out);
}

// round 7
// speedup vs baseline: 2.5976x; 1.0080x over previous
#include <cuda_runtime.h>
#include <cuda_bf16.h>
#include <cstdint>

#define N_NODES 100000
#define N_EDGES 3200000
#define BATCH   16
#define HIDDEN  64

// Lookup table for the scalar MLP f(x): 1 -> 64 GELU(erf) -> 1
#define TBL_N     16384
#define TBL_RANGE 10.0f
#define TBL_SCALE ((float)TBL_N / (2.0f * TBL_RANGE))
#define TBL_OFF   ((float)TBL_N * 0.5f)

#define TBL_BLOCKS  ((TBL_N + 1 + 255) / 256)       // 65
#define PREP_BLOCKS ((N_NODES + 255) / 256)         // 391
#define DEG_BLOCKS  ((N_EDGES + 255) / 256)         // 12500

// Scratch (device globals; zero-initialized at module load).
// INVARIANT: g_agg and g_deg are all-zero at kernel_launch entry —
// guaranteed by loader zero-init on the first call and by mlp_kernel's
// consume-and-reset on every call thereafter.
__device__ __align__(16) float g_muT[(size_t)N_NODES * BATCH];  // mu transposed [N][B]
__device__ __align__(16) float g_agg[(size_t)N_NODES * BATCH];  // accumulators  [N][B]
__device__ float g_deg[N_NODES];                                // degree counts
__device__ float g_tbl[TBL_N + 2];                              // f(x) samples

// ---------------------------------------------------------------------------
// Exact scalar MLP (erf GELU) — table build + rare out-of-range fallback.
// ---------------------------------------------------------------------------
__device__ __forceinline__ float mlp_exact(float x,
                                           const float* __restrict__ W1,
                                           const float* __restrict__ b1,
                                           const float* __restrict__ W2,
                                           const float* __restrict__ b2) {
    float acc = b2[0];
    #pragma unroll 8
    for (int h = 0; h < HIDDEN; h++) {
        const float z = fmaf(x, __ldg(W1 + h), __ldg(b1 + h));
        const float g = 0.5f * z * (1.0f + erff(z * 0.70710678118654752440f));
        acc = fmaf(g, __ldg(W2 + h), acc);
    }
    return acc;
}

__device__ __forceinline__ float lut_eval(float x,
                                          const float* __restrict__ W1,
                                          const float* __restrict__ b1,
                                          const float* __restrict__ W2,
                                          const float* __restrict__ b2) {
    const float u = fmaf(x, TBL_SCALE, TBL_OFF);
    if (u >= 0.0f && u < (float)TBL_N) {
        const int   i    = (int)u;
        const float frac = u - (float)i;
        const float t0 = __ldg(g_tbl + i);
        const float t1 = __ldg(g_tbl + i + 1);
        return fmaf(t1 - t0, frac, t0);
    }
    return mlp_exact(x, W1, b1, W2, b2);   // |x| > 10: essentially never
}

// ---------------------------------------------------------------------------
// Kernel 1 (merged, 3 block ranges):
//   [0, TBL_BLOCKS)                      build the LUT        (MUFU/FMA)
//   [TBL_BLOCKS, +PREP_BLOCKS)           transpose mu -> muT  (memory)
//   [TBL_BLOCKS+PREP_BLOCKS, +DEG_BLOCKS) degree histogram     (L2 REDs)
// The three overlap across SMs; deg REDs hide under transpose traffic.
// g_deg is zero at entry (consume-and-reset invariant).
// ---------------------------------------------------------------------------
__global__ void __launch_bounds__(256) init_kernel(const float* __restrict__ mu,
                                                   const int*   __restrict__ ei,
                                                   const float* __restrict__ W1,
                                                   const float* __restrict__ b1,
                                                   const float* __restrict__ W2,
                                                   const float* __restrict__ b2) {
    if (blockIdx.x < TBL_BLOCKS) {
        const int i = blockIdx.x * 256 + threadIdx.x;
        if (i <= TBL_N) {
            const float x = -TBL_RANGE + (2.0f * TBL_RANGE / (float)TBL_N) * (float)i;
            g_tbl[i] = mlp_exact(x, W1, b1, W2, b2);
        }
        return;
    }

    if (blockIdx.x < TBL_BLOCKS + PREP_BLOCKS) {
        const int n = (blockIdx.x - TBL_BLOCKS) * 256 + threadIdx.x;
        if (n >= N_NODES) return;

        float v[BATCH];
        #pragma unroll
        for (int b = 0; b < BATCH; b++)
            v[b] = __ldg(mu + (size_t)b * N_NODES + n);

        float4* dst = reinterpret_cast<float4*>(g_muT) + (size_t)n * 4;
        dst[0] = make_float4(v[0],  v[1],  v[2],  v[3]);
        dst[1] = make_float4(v[4],  v[5],  v[6],  v[7]);
        dst[2] = make_float4(v[8],  v[9],  v[10], v[11]);
        dst[3] = make_float4(v[12], v[13], v[14], v[15]);
        return;
    }

    // degree histogram range
    const int e = (blockIdx.x - TBL_BLOCKS - PREP_BLOCKS) * 256 + threadIdx.x;
    if (e >= N_EDGES) return;
    const int r = __ldg(ei + e);
    if ((unsigned)r < N_NODES) {
        asm volatile("red.global.add.f32 [%0], %1;"
                     :: "l"(__cvta_generic_to_global(g_deg + r)), "f"(1.0f)
                     : "memory");
    }
}

// ---------------------------------------------------------------------------
// Kernel 2: per-edge scatter, 4 lanes per edge (8 edges per warp).
// Pure gather + v4-RED now (deg moved to init).
// ---------------------------------------------------------------------------
__device__ __forceinline__ void red_add_v4(float* gptr, float4 v) {
    asm volatile("red.global.add.v4.f32 [%0], {%1, %2, %3, %4};"
                 :: "l"(__cvta_generic_to_global(gptr)),
                    "f"(v.x), "f"(v.y), "f"(v.z), "f"(v.w)
                 : "memory");
}

__global__ void __launch_bounds__(256) edge_kernel(const int* __restrict__ ei) {
    const int T = blockIdx.x * blockDim.x + threadIdx.x;
    const int e = T >> 2;        // edge id
    const int q = T & 3;         // float4 slot within the 64B row
    if (e >= N_EDGES) return;

    const int r = __ldg(ei + e);             // destination (row)
    const int c = __ldg(ei + N_EDGES + e);   // source (col)
    if ((unsigned)r >= N_NODES || (unsigned)c >= N_NODES) return;

    const float4 v = reinterpret_cast<const float4*>(g_muT)[(size_t)c * 4 + q];
    red_add_v4(g_agg + (size_t)r * BATCH + q * 4, v);
}

// ---------------------------------------------------------------------------
// Kernel 3: mean + LUT MLP, vectorized (one thread = 4 batches of one node),
// then CONSUME-AND-RESET: writes zeros back to g_agg / g_deg so the next
// invocation (graph replay) starts from a clean state without a zeroing pass.
// ---------------------------------------------------------------------------
__global__ void __launch_bounds__(512) mlp_kernel(const float* __restrict__ W1,
                                                  const float* __restrict__ b1,
                                                  const float* __restrict__ W2,
                                                  const float* __restrict__ b2,
                                                  float* __restrict__ out) {
    __shared__ float tileY[BATCH][128 + 4];

    const int t    = threadIdx.x;
    const int n0   = blockIdx.x * 128;
    const int node = t >> 2;
    const int q    = t & 3;
    const int n    = n0 + node;

    float4 y = make_float4(0.f, 0.f, 0.f, 0.f);
    if (n < N_NODES) {
        const float invd = 1.0f / fmaxf(g_deg[n], 1.0f);
        float4* aggp = reinterpret_cast<float4*>(g_agg) + (size_t)n * 4 + q;
        const float4 a = *aggp;
        *aggp = make_float4(0.f, 0.f, 0.f, 0.f);     // reset for next replay
        if (q == 0) g_deg[n] = 0.0f;                 // reset for next replay
        y.x = lut_eval(a.x * invd, W1, b1, W2, b2);
        y.y = lut_eval(a.y * invd, W1, b1, W2, b2);
        y.z = lut_eval(a.z * invd, W1, b1, W2, b2);
        y.w = lut_eval(a.w * invd, W1, b1, W2, b2);
    }
    tileY[q * 4 + 0][node] = y.x;
    tileY[q * 4 + 1][node] = y.y;
    tileY[q * 4 + 2][node] = y.z;
    tileY[q * 4 + 3][node] = y.w;
    __syncthreads();

    const int j = t & 127;
    #pragma unroll
    for (int r = 0; r < 4; r++) {
        const int b  = (t >> 7) + r * 4;
        const int nn = n0 + j;
        if (nn < N_NODES) out[(size_t)b * N_NODES + nn] = tileY[b][j];
    }
}

// ---------------------------------------------------------------------------
extern "C" void kernel_launch(void* const* d_in, const int* in_sizes, int n_in,
                              void* d_out, int out_size) {
    const float* mu = (const float*)d_in[0];
    const int*   ei = (const int*)d_in[1];     // edge_index stored as int32
    const float* W1 = (const float*)d_in[2];
    const float* b1 = (const float*)d_in[3];
    const float* W2 = (const float*)d_in[4];
    const float* b2 = (const float*)d_in[5];
    float*      out = (float*)d_out;

    init_kernel<<<TBL_BLOCKS + PREP_BLOCKS + DEG_BLOCKS, 256>>>(mu, ei, W1, b1, W2, b2);

    const long long lanes = (long long)N_EDGES * 4;
    edge_kernel<<<(int)((lanes + 255) / 256), 256>>>(ei);

    mlp_kernel<<<(N_NODES + 127) / 128, 512>>>(W1, b1, W2, b2, out);
}